// round 1
// baseline (speedup 1.0000x reference)
#include <cuda_runtime.h>
#include <math.h>

#define T_     2048
#define EMB_   1024
#define HEADS_ 16
#define HD_    64
#define B_     2
#define M_     (B_*T_)      // 4096
#define BH_    (B_*HEADS_)  // 32

// Scratch (device globals; no runtime allocation allowed)
__device__ float g_Q[BH_*HD_*T_];   // [bh][d][t]  (transposed for coalesced flash loads)
__device__ float g_K[BH_*HD_*T_];   // [bh][d][t]
__device__ float g_V[BH_*T_*HD_];   // [bh][t][d]
__device__ float g_A[M_*EMB_];      // attention output, [b*T+t][emb]

// ---------------------------------------------------------------------------
// 64x64x16 SGEMM: out = A[M,1024] @ W[N,1024]^T + bias, with layout modes:
//   mode 0: store to [bh][d][t]   (Q, K)
//   mode 1: store to [bh][t][d]   (V)
//   mode 2: store to [r][n] plain (attn-out projection -> d_out)
// ---------------------------------------------------------------------------
__global__ void gemm64(const float* __restrict__ A, const float* __restrict__ W,
                       const float* __restrict__ bias, float* __restrict__ out,
                       int mode)
{
    __shared__ float As[16][64];
    __shared__ float Bs[16][64];

    const int tid = threadIdx.x;
    const int tx  = tid & 15;
    const int ty  = tid >> 4;
    const int m0  = blockIdx.y << 6;
    const int n0  = blockIdx.x << 6;

    const int lr = tid >> 2;          // 0..63: tile row
    const int lk = (tid & 3) << 2;    // 0,4,8,12: k-offset

    const float* Ap = A + (m0 + lr) * EMB_ + lk;
    const float* Wp = W + (n0 + lr) * EMB_ + lk;

    float acc[4][4] = {};

    for (int k0 = 0; k0 < EMB_; k0 += 16) {
        float4 av = *(const float4*)(Ap + k0);
        float4 wv = *(const float4*)(Wp + k0);
        __syncthreads();
        As[lk+0][lr]=av.x; As[lk+1][lr]=av.y; As[lk+2][lr]=av.z; As[lk+3][lr]=av.w;
        Bs[lk+0][lr]=wv.x; Bs[lk+1][lr]=wv.y; Bs[lk+2][lr]=wv.z; Bs[lk+3][lr]=wv.w;
        __syncthreads();
#pragma unroll
        for (int kk = 0; kk < 16; kk++) {
            float a4[4], b4[4];
            *(float4*)a4 = *(const float4*)&As[kk][ty << 2];
            *(float4*)b4 = *(const float4*)&Bs[kk][tx << 2];
#pragma unroll
            for (int i = 0; i < 4; i++)
#pragma unroll
                for (int j = 0; j < 4; j++)
                    acc[i][j] += a4[i] * b4[j];
        }
    }

    float bs4[4];
#pragma unroll
    for (int j = 0; j < 4; j++) bs4[j] = bias[n0 + (tx << 2) + j];

#pragma unroll
    for (int i = 0; i < 4; i++) {
        const int r     = m0 + (ty << 2) + i;
        const int b_idx = r >> 11;        // r / T_
        const int t     = r & (T_ - 1);
#pragma unroll
        for (int j = 0; j < 4; j++) {
            const int n = n0 + (tx << 2) + j;
            const float v = acc[i][j] + bs4[j];
            if (mode == 0) {
                const int bh = b_idx * HEADS_ + (n >> 6);
                out[(bh * HD_ + (n & 63)) * T_ + t] = v;
            } else if (mode == 1) {
                const int bh = b_idx * HEADS_ + (n >> 6);
                out[(bh * T_ + t) * HD_ + (n & 63)] = v;
            } else {
                out[r * EMB_ + n] = v;
            }
        }
    }
}

// ---------------------------------------------------------------------------
// fp32 flash attention, causal. Block = 64 q-rows; loops over k-tiles <= q-tile.
// Q/K come in [bh][d][t]; V in [bh][t][d]. Output -> g_A [b*T+t][h*64+d].
// Dynamic smem: Qs[64][64] + Kt[64][64] + Vs[64][64] + Pt[64][65]
// ---------------------------------------------------------------------------
#define FLASH_SMEM ((3*64*64 + 64*65) * 4)   // 65792 bytes

__global__ void flash_attn(const float* __restrict__ Q, const float* __restrict__ K,
                           const float* __restrict__ V, float* __restrict__ out)
{
    extern __shared__ float sm[];
    float* Qs = sm;            // [d][r]  (pre-scaled by 1/8)
    float* Kt = sm + 4096;     // [d][c]
    float* Vs = sm + 8192;     // [c][d]
    float* Pt = sm + 12288;    // [c][r], row stride 65

    const int qi  = blockIdx.x;
    const int bh  = blockIdx.y;
    const int tid = threadIdx.x;
    const int tx  = tid & 15;
    const int ty  = tid >> 4;
    const int q0  = qi << 6;

    const float* Qg = Q + bh * HD_ * T_;
    const float* Kg = K + bh * HD_ * T_;

#pragma unroll
    for (int it = 0; it < 4; it++) {
        int e  = tid + (it << 8);
        int d  = e >> 4;
        int r4 = (e & 15) << 2;
        float4 v = *(const float4*)&Qg[d * T_ + q0 + r4];
        v.x *= 0.125f; v.y *= 0.125f; v.z *= 0.125f; v.w *= 0.125f;
        *(float4*)&Qs[(d << 6) + r4] = v;
    }

    float o[4][4] = {};
    float mi[4], li[4];
#pragma unroll
    for (int i = 0; i < 4; i++) { mi[i] = -1e30f; li[i] = 0.f; }

    for (int jt = 0; jt <= qi; jt++) {
        const int k0 = jt << 6;
        __syncthreads();   // previous iter's consumers done before overwrite
#pragma unroll
        for (int it = 0; it < 4; it++) {
            int e  = tid + (it << 8);
            int d  = e >> 4;
            int r4 = (e & 15) << 2;
            *(float4*)&Kt[(d << 6) + r4] = *(const float4*)&Kg[d * T_ + k0 + r4];
        }
        const float* Vg = V + (bh * T_ + k0) * HD_;
#pragma unroll
        for (int it = 0; it < 4; it++) {
            int e = tid + (it << 8);
            *(float4*)&Vs[e << 2] = *(const float4*)&Vg[e << 2];
        }
        __syncthreads();

        // S = (Q/8) @ K^T for this 64x64 tile
        float s[4][4] = {};
#pragma unroll 8
        for (int kk = 0; kk < 64; kk++) {
            float a4[4], b4[4];
            *(float4*)a4 = *(const float4*)&Qs[(kk << 6) + (ty << 2)];
            *(float4*)b4 = *(const float4*)&Kt[(kk << 6) + (tx << 2)];
#pragma unroll
            for (int i = 0; i < 4; i++)
#pragma unroll
                for (int j = 0; j < 4; j++)
                    s[i][j] += a4[i] * b4[j];
        }

        if (jt == qi) {   // causal mask on the diagonal tile
#pragma unroll
            for (int i = 0; i < 4; i++)
#pragma unroll
                for (int j = 0; j < 4; j++)
                    if (((tx << 2) + j) > ((ty << 2) + i)) s[i][j] = -1e30f;
        }

        // online softmax: row stats shared by the 16 tx-threads of each ty group
        float mnew[4], fac[4];
#pragma unroll
        for (int i = 0; i < 4; i++) {
            float v = fmaxf(fmaxf(s[i][0], s[i][1]), fmaxf(s[i][2], s[i][3]));
#pragma unroll
            for (int off = 8; off > 0; off >>= 1)
                v = fmaxf(v, __shfl_xor_sync(0xffffffffu, v, off));
            mnew[i] = fmaxf(mi[i], v);
            fac[i]  = __expf(mi[i] - mnew[i]);
            mi[i]   = mnew[i];
        }
#pragma unroll
        for (int i = 0; i < 4; i++) {
            float r = 0.f;
#pragma unroll
            for (int j = 0; j < 4; j++) {
                float p = __expf(s[i][j] - mnew[i]);
                r += p;
                Pt[((tx << 2) + j) * 65 + (ty << 2) + i] = p;
            }
#pragma unroll
            for (int off = 8; off > 0; off >>= 1)
                r += __shfl_xor_sync(0xffffffffu, r, off);
            li[i] = li[i] * fac[i] + r;
#pragma unroll
            for (int j = 0; j < 4; j++) o[i][j] *= fac[i];
        }
        __syncthreads();   // Pt visible

        // O += P @ V
#pragma unroll 4
        for (int c = 0; c < 64; c++) {
            float b4[4];
            *(float4*)b4 = *(const float4*)&Vs[(c << 6) + (tx << 2)];
#pragma unroll
            for (int i = 0; i < 4; i++) {
                float p = Pt[c * 65 + (ty << 2) + i];
#pragma unroll
                for (int j = 0; j < 4; j++) o[i][j] += p * b4[j];
            }
        }
    }

    const int b_idx = bh >> 4;
    const int h     = bh & 15;
#pragma unroll
    for (int i = 0; i < 4; i++) {
        const float inv = 1.f / li[i];
        const int t = q0 + (ty << 2) + i;
#pragma unroll
        for (int j = 0; j < 4; j++)
            out[(b_idx * T_ + t) * EMB_ + (h << 6) + (tx << 2) + j] = o[i][j] * inv;
    }
}

// ---------------------------------------------------------------------------
extern "C" void kernel_launch(void* const* d_in, const int* in_sizes, int n_in,
                              void* d_out, int out_size)
{
    const float* x  = (const float*)d_in[0];
    const float* Wq = (const float*)d_in[1];
    const float* bq = (const float*)d_in[2];
    const float* Wk = (const float*)d_in[3];
    const float* bk = (const float*)d_in[4];
    const float* Wv = (const float*)d_in[5];
    const float* bv = (const float*)d_in[6];
    const float* Wo = (const float*)d_in[7];
    const float* bo = (const float*)d_in[8];
    float* out = (float*)d_out;

    float *qp, *kp, *vp, *ap;
    cudaGetSymbolAddress((void**)&qp, g_Q);
    cudaGetSymbolAddress((void**)&kp, g_K);
    cudaGetSymbolAddress((void**)&vp, g_V);
    cudaGetSymbolAddress((void**)&ap, g_A);

    static_assert(FLASH_SMEM <= 227 * 1024, "smem");
    cudaFuncSetAttribute(flash_attn, cudaFuncAttributeMaxDynamicSharedMemorySize, FLASH_SMEM);

    dim3 blk(256);
    dim3 gg(EMB_ / 64, M_ / 64);        // (16, 64)

    gemm64<<<gg, blk>>>(x, Wq, bq, qp, 0);
    gemm64<<<gg, blk>>>(x, Wk, bk, kp, 0);
    gemm64<<<gg, blk>>>(x, Wv, bv, vp, 1);

    flash_attn<<<dim3(T_ / 64, BH_), blk, FLASH_SMEM>>>(qp, kp, vp, ap);

    gemm64<<<gg, blk>>>(ap, Wo, bo, out, 2);
}

// round 3
// speedup vs baseline: 1.5233x; 1.5233x over previous
#include <cuda_runtime.h>
#include <cuda_bf16.h>
#include <stdint.h>
#include <math.h>

#define T_     2048
#define EMB_   1024
#define HEADS_ 16
#define HD_    64
#define B_     2
#define M_     (B_*T_)      // 4096
#define BH_    (B_*HEADS_)  // 32

// ---------------- scratch (device globals; no runtime alloc allowed) -------
__device__ float g_Q[BH_*HD_*T_];   // [bh][d][t]
__device__ float g_K[BH_*HD_*T_];   // [bh][d][t]
__device__ float g_V[BH_*T_*HD_];   // [bh][t][d]
__device__ float g_A[M_*EMB_];      // attention output [m][emb]

__device__ __nv_bfloat16 g_xh[M_*EMB_],  g_xl[M_*EMB_];
__device__ __nv_bfloat16 g_ah[M_*EMB_],  g_al[M_*EMB_];
__device__ __nv_bfloat16 g_wh[3*EMB_*EMB_], g_wl[3*EMB_*EMB_];
__device__ __nv_bfloat16 g_woh[EMB_*EMB_],  g_wol[EMB_*EMB_];

// ---------------- helpers ---------------------------------------------------
__device__ __forceinline__ uint32_t smem_u32(const void* p) {
    uint32_t a;
    asm("{ .reg .u64 t; cvta.to.shared.u64 t, %1; cvt.u32.u64 %0, t; }" : "=r"(a) : "l"(p));
    return a;
}
__device__ __forceinline__ void cp16(uint32_t dst, const void* src) {
    asm volatile("cp.async.cg.shared.global [%0], [%1], 16;" :: "r"(dst), "l"(src));
}
__device__ __forceinline__ void cp_commit() { asm volatile("cp.async.commit_group;" ::: "memory"); }
template<int N> __device__ __forceinline__ void cp_wait() {
    asm volatile("cp.async.wait_group %0;" :: "n"(N) : "memory");
}
__device__ __forceinline__ void mma16816(float* c, const uint32_t* a, const uint32_t* b) {
    asm volatile("mma.sync.aligned.m16n8k16.row.col.f32.bf16.bf16.f32 "
        "{%0,%1,%2,%3}, {%4,%5,%6,%7}, {%8,%9}, {%0,%1,%2,%3};"
        : "+f"(c[0]), "+f"(c[1]), "+f"(c[2]), "+f"(c[3])
        : "r"(a[0]), "r"(a[1]), "r"(a[2]), "r"(a[3]), "r"(b[0]), "r"(b[1]));
}

// ---------------- fp32 -> bf16 hi/lo split ----------------------------------
__global__ void splitf32(const float* __restrict__ s, __nv_bfloat16* __restrict__ h,
                         __nv_bfloat16* __restrict__ l, int n)
{
    int i = (blockIdx.x * blockDim.x + threadIdx.x) << 2;
    if (i >= n) return;
    float4 v = *(const float4*)(s + i);
    __nv_bfloat16 h0 = __float2bfloat16(v.x), h1 = __float2bfloat16(v.y);
    __nv_bfloat16 h2 = __float2bfloat16(v.z), h3 = __float2bfloat16(v.w);
    __nv_bfloat16 l0 = __float2bfloat16(v.x - __bfloat162float(h0));
    __nv_bfloat16 l1 = __float2bfloat16(v.y - __bfloat162float(h1));
    __nv_bfloat16 l2 = __float2bfloat16(v.z - __bfloat162float(h2));
    __nv_bfloat16 l3 = __float2bfloat16(v.w - __bfloat162float(h3));
    __nv_bfloat162* H = (__nv_bfloat162*)(h + i);
    __nv_bfloat162* L = (__nv_bfloat162*)(l + i);
    H[0] = __nv_bfloat162(h0, h1); H[1] = __nv_bfloat162(h2, h3);
    L[0] = __nv_bfloat162(l0, l1); L[1] = __nv_bfloat162(l2, l3);
}

// ---------------- mma.sync GEMM: 128x128 tile, K=1024, hi/lo split ----------
// out = A @ W^T + bias.
// MODE 0: blockIdx.z in {0,1,2} -> Q/K ([bh][d][t]) z<2, V ([bh][t][d]) z=2
// MODE 1: plain row-major [m][n]
#define BK       32
#define NCHUNK   (EMB_/BK)          // 32
#define STRIDE   40                 // bf16 row stride (padded)
#define HALF_E   (128*STRIDE)       // elements per matrix-half
#define BUF_E    (4*HALF_E)         // Ah,Al,Bh,Bl
#define GEMM_SMEM (2*BUF_E*2)       // bytes, two buffers

template<int MODE>
__global__ void __launch_bounds__(256) gemm_mma(
    const __nv_bfloat16* __restrict__ Ah, const __nv_bfloat16* __restrict__ Al,
    const __nv_bfloat16* __restrict__ Wh, const __nv_bfloat16* __restrict__ Wl,
    const float* __restrict__ bias0, const float* __restrict__ bias1,
    const float* __restrict__ bias2,
    float* __restrict__ out0, float* __restrict__ out1, float* __restrict__ out2)
{
    extern __shared__ __nv_bfloat16 smem[];
    const int tid  = threadIdx.x;
    const int lane = tid & 31;
    const int wid  = tid >> 5;
    const int wm   = wid >> 2;          // 0..1
    const int wn   = wid & 3;           // 0..3
    const int m0   = blockIdx.y << 7;
    const int n0   = blockIdx.x << 7;
    const int z    = (MODE == 0) ? (int)blockIdx.z : 0;

    const __nv_bfloat16* wh = Wh + (size_t)z * EMB_ * EMB_;
    const __nv_bfloat16* wl = Wl + (size_t)z * EMB_ * EMB_;
    const float* bias = (MODE == 0) ? (z == 0 ? bias0 : (z == 1 ? bias1 : bias2)) : bias0;
    float* out        = (MODE == 0) ? (z == 0 ? out0  : (z == 1 ? out1  : out2 )) : out0;

    const uint32_t sb = smem_u32(smem);

    // load-thread mapping: row r = tid&127, two 16B segs starting at (tid>>7)*2
    const int lr = tid & 127;
    const int s0 = (tid >> 7) << 1;
    const __nv_bfloat16* gAh = Ah + (size_t)(m0 + lr) * EMB_;
    const __nv_bfloat16* gAl = Al + (size_t)(m0 + lr) * EMB_;
    const __nv_bfloat16* gBh = wh + (size_t)(n0 + lr) * EMB_;
    const __nv_bfloat16* gBl = wl + (size_t)(n0 + lr) * EMB_;
    const uint32_t drow = (uint32_t)lr * (STRIDE * 2);   // bytes

    auto load_chunk = [&](int kc, int buf) {
        const uint32_t base = sb + (uint32_t)buf * (BUF_E * 2);
        const int ke = kc * BK;
#pragma unroll
        for (int s = s0; s < s0 + 2; s++) {
            const uint32_t doff = drow + (uint32_t)s * 16;
            cp16(base + 0*(HALF_E*2) + doff, gAh + ke + s*8);
            cp16(base + 1*(HALF_E*2) + doff, gAl + ke + s*8);
            cp16(base + 2*(HALF_E*2) + doff, gBh + ke + s*8);
            cp16(base + 3*(HALF_E*2) + doff, gBl + ke + s*8);
        }
        cp_commit();
    };

    float acc[4][4][4] = {};

    load_chunk(0, 0);

    for (int kc = 0; kc < NCHUNK; kc++) {
        const int buf = kc & 1;
        if (kc + 1 < NCHUNK) { load_chunk(kc + 1, buf ^ 1); cp_wait<1>(); }
        else                 { cp_wait<0>(); }
        __syncthreads();

        const __nv_bfloat16* sAh = smem + buf * BUF_E;
        const __nv_bfloat16* sAl = sAh + HALF_E;
        const __nv_bfloat16* sBh = sAh + 2*HALF_E;
        const __nv_bfloat16* sBl = sAh + 3*HALF_E;

#pragma unroll
        for (int ks = 0; ks < 2; ks++) {
            const int kk = ks * 16 + ((lane & 3) << 1);
            uint32_t bh_[4][2], bl_[4][2];
#pragma unroll
            for (int nf = 0; nf < 4; nf++) {
                const int n = wn * 32 + nf * 8 + (lane >> 2);
                bh_[nf][0] = *(const uint32_t*)&sBh[n * STRIDE + kk];
                bh_[nf][1] = *(const uint32_t*)&sBh[n * STRIDE + kk + 8];
                bl_[nf][0] = *(const uint32_t*)&sBl[n * STRIDE + kk];
                bl_[nf][1] = *(const uint32_t*)&sBl[n * STRIDE + kk + 8];
            }
#pragma unroll
            for (int mf = 0; mf < 4; mf++) {
                const int mr = wm * 64 + mf * 16 + (lane >> 2);
                uint32_t ah[4], al[4];
                ah[0] = *(const uint32_t*)&sAh[ mr      * STRIDE + kk];
                ah[1] = *(const uint32_t*)&sAh[(mr + 8) * STRIDE + kk];
                ah[2] = *(const uint32_t*)&sAh[ mr      * STRIDE + kk + 8];
                ah[3] = *(const uint32_t*)&sAh[(mr + 8) * STRIDE + kk + 8];
                al[0] = *(const uint32_t*)&sAl[ mr      * STRIDE + kk];
                al[1] = *(const uint32_t*)&sAl[(mr + 8) * STRIDE + kk];
                al[2] = *(const uint32_t*)&sAl[ mr      * STRIDE + kk + 8];
                al[3] = *(const uint32_t*)&sAl[(mr + 8) * STRIDE + kk + 8];
#pragma unroll
                for (int nf = 0; nf < 4; nf++) {
                    mma16816(acc[mf][nf], ah, bh_[nf]);
                    mma16816(acc[mf][nf], ah, bl_[nf]);
                    mma16816(acc[mf][nf], al, bh_[nf]);
                }
            }
        }
        __syncthreads();
    }

    // -------- epilogue --------
#pragma unroll
    for (int mf = 0; mf < 4; mf++) {
#pragma unroll
        for (int nf = 0; nf < 4; nf++) {
#pragma unroll
            for (int half = 0; half < 2; half++) {
                const int m = m0 + wm * 64 + mf * 16 + (lane >> 2) + half * 8;
                const int n = n0 + wn * 32 + nf * 8 + ((lane & 3) << 1);
                const float v0 = acc[mf][nf][half*2 + 0] + bias[n];
                const float v1 = acc[mf][nf][half*2 + 1] + bias[n + 1];
                const int bb = m >> 11;
                const int t  = m & (T_ - 1);
                if (MODE == 0) {
                    const int h = n >> 6, d = n & 63;
                    const int bh = bb * HEADS_ + h;
                    if (z < 2) {     // Q/K: [bh][d][t]
                        float* p = out + ((size_t)(bh * HD_ + d)) * T_ + t;
                        p[0] = v0; p[T_] = v1;
                    } else {         // V: [bh][t][d]
                        *(float2*)&out[((size_t)bh * T_ + t) * HD_ + d] =
                            make_float2(v0, v1);
                    }
                } else {
                    *(float2*)&out[(size_t)m * EMB_ + n] = make_float2(v0, v1);
                }
            }
        }
    }
}

// ---------------- fp32 flash attention (round-1, unchanged) -----------------
#define FLASH_SMEM ((3*64*64 + 64*65) * 4)

__global__ void flash_attn(const float* __restrict__ Q, const float* __restrict__ K,
                           const float* __restrict__ V, float* __restrict__ out)
{
    extern __shared__ float sm[];
    float* Qs = sm;
    float* Kt = sm + 4096;
    float* Vs = sm + 8192;
    float* Pt = sm + 12288;

    const int qi  = blockIdx.x;
    const int bh  = blockIdx.y;
    const int tid = threadIdx.x;
    const int tx  = tid & 15;
    const int ty  = tid >> 4;
    const int q0  = qi << 6;

    const float* Qg = Q + bh * HD_ * T_;
    const float* Kg = K + bh * HD_ * T_;

#pragma unroll
    for (int it = 0; it < 4; it++) {
        int e  = tid + (it << 8);
        int d  = e >> 4;
        int r4 = (e & 15) << 2;
        float4 v = *(const float4*)&Qg[d * T_ + q0 + r4];
        v.x *= 0.125f; v.y *= 0.125f; v.z *= 0.125f; v.w *= 0.125f;
        *(float4*)&Qs[(d << 6) + r4] = v;
    }

    float o[4][4] = {};
    float mi[4], li[4];
#pragma unroll
    for (int i = 0; i < 4; i++) { mi[i] = -1e30f; li[i] = 0.f; }

    for (int jt = 0; jt <= qi; jt++) {
        const int k0 = jt << 6;
        __syncthreads();
#pragma unroll
        for (int it = 0; it < 4; it++) {
            int e  = tid + (it << 8);
            int d  = e >> 4;
            int r4 = (e & 15) << 2;
            *(float4*)&Kt[(d << 6) + r4] = *(const float4*)&Kg[d * T_ + k0 + r4];
        }
        const float* Vg = V + (bh * T_ + k0) * HD_;
#pragma unroll
        for (int it = 0; it < 4; it++) {
            int e = tid + (it << 8);
            *(float4*)&Vs[e << 2] = *(const float4*)&Vg[e << 2];
        }
        __syncthreads();

        float s[4][4] = {};
#pragma unroll 8
        for (int kk = 0; kk < 64; kk++) {
            float a4[4], b4[4];
            *(float4*)a4 = *(const float4*)&Qs[(kk << 6) + (ty << 2)];
            *(float4*)b4 = *(const float4*)&Kt[(kk << 6) + (tx << 2)];
#pragma unroll
            for (int i = 0; i < 4; i++)
#pragma unroll
                for (int j = 0; j < 4; j++)
                    s[i][j] += a4[i] * b4[j];
        }

        if (jt == qi) {
#pragma unroll
            for (int i = 0; i < 4; i++)
#pragma unroll
                for (int j = 0; j < 4; j++)
                    if (((tx << 2) + j) > ((ty << 2) + i)) s[i][j] = -1e30f;
        }

        float mnew[4], fac[4];
#pragma unroll
        for (int i = 0; i < 4; i++) {
            float v = fmaxf(fmaxf(s[i][0], s[i][1]), fmaxf(s[i][2], s[i][3]));
#pragma unroll
            for (int off = 8; off > 0; off >>= 1)
                v = fmaxf(v, __shfl_xor_sync(0xffffffffu, v, off));
            mnew[i] = fmaxf(mi[i], v);
            fac[i]  = __expf(mi[i] - mnew[i]);
            mi[i]   = mnew[i];
        }
#pragma unroll
        for (int i = 0; i < 4; i++) {
            float r = 0.f;
#pragma unroll
            for (int j = 0; j < 4; j++) {
                float p = __expf(s[i][j] - mnew[i]);
                r += p;
                Pt[((tx << 2) + j) * 65 + (ty << 2) + i] = p;
            }
#pragma unroll
            for (int off = 8; off > 0; off >>= 1)
                r += __shfl_xor_sync(0xffffffffu, r, off);
            li[i] = li[i] * fac[i] + r;
#pragma unroll
            for (int j = 0; j < 4; j++) o[i][j] *= fac[i];
        }
        __syncthreads();

#pragma unroll 4
        for (int c = 0; c < 64; c++) {
            float b4[4];
            *(float4*)b4 = *(const float4*)&Vs[(c << 6) + (tx << 2)];
#pragma unroll
            for (int i = 0; i < 4; i++) {
                float p = Pt[c * 65 + (ty << 2) + i];
#pragma unroll
                for (int j = 0; j < 4; j++) o[i][j] += p * b4[j];
            }
        }
    }

    const int b_idx = bh >> 4;
    const int h     = bh & 15;
#pragma unroll
    for (int i = 0; i < 4; i++) {
        const float inv = 1.f / li[i];
        const int t = q0 + (ty << 2) + i;
#pragma unroll
        for (int j = 0; j < 4; j++)
            out[(b_idx * T_ + t) * EMB_ + (h << 6) + (tx << 2) + j] = o[i][j] * inv;
    }
}

// ---------------------------------------------------------------------------
extern "C" void kernel_launch(void* const* d_in, const int* in_sizes, int n_in,
                              void* d_out, int out_size)
{
    const float* x  = (const float*)d_in[0];
    const float* Wq = (const float*)d_in[1];
    const float* bq = (const float*)d_in[2];
    const float* Wk = (const float*)d_in[3];
    const float* bk = (const float*)d_in[4];
    const float* Wv = (const float*)d_in[5];
    const float* bv = (const float*)d_in[6];
    const float* Wo = (const float*)d_in[7];
    const float* bo = (const float*)d_in[8];
    float* out = (float*)d_out;

    float *qp, *kp, *vp, *ap;
    __nv_bfloat16 *xh, *xl, *ah, *al, *wh, *wl, *woh, *wol;
    cudaGetSymbolAddress((void**)&qp,  g_Q);
    cudaGetSymbolAddress((void**)&kp,  g_K);
    cudaGetSymbolAddress((void**)&vp,  g_V);
    cudaGetSymbolAddress((void**)&ap,  g_A);
    cudaGetSymbolAddress((void**)&xh,  g_xh);
    cudaGetSymbolAddress((void**)&xl,  g_xl);
    cudaGetSymbolAddress((void**)&ah,  g_ah);
    cudaGetSymbolAddress((void**)&al,  g_al);
    cudaGetSymbolAddress((void**)&wh,  g_wh);
    cudaGetSymbolAddress((void**)&wl,  g_wl);
    cudaGetSymbolAddress((void**)&woh, g_woh);
    cudaGetSymbolAddress((void**)&wol, g_wol);

    cudaFuncSetAttribute(flash_attn,  cudaFuncAttributeMaxDynamicSharedMemorySize, FLASH_SMEM);
    cudaFuncSetAttribute(gemm_mma<0>, cudaFuncAttributeMaxDynamicSharedMemorySize, GEMM_SMEM);
    cudaFuncSetAttribute(gemm_mma<1>, cudaFuncAttributeMaxDynamicSharedMemorySize, GEMM_SMEM);

    const int NE = M_ * EMB_;
    const int NW = EMB_ * EMB_;
    dim3 cblk(256);

    splitf32<<<(NE/4 + 255)/256, cblk>>>(x,  xh,  xl,  NE);
    splitf32<<<(NW/4 + 255)/256, cblk>>>(Wq, wh + 0*(size_t)NW, wl + 0*(size_t)NW, NW);
    splitf32<<<(NW/4 + 255)/256, cblk>>>(Wk, wh + 1*(size_t)NW, wl + 1*(size_t)NW, NW);
    splitf32<<<(NW/4 + 255)/256, cblk>>>(Wv, wh + 2*(size_t)NW, wl + 2*(size_t)NW, NW);
    splitf32<<<(NW/4 + 255)/256, cblk>>>(Wo, woh, wol, NW);

    gemm_mma<0><<<dim3(EMB_/128, M_/128, 3), 256, GEMM_SMEM>>>(
        xh, xl, wh, wl, bq, bk, bv, qp, kp, vp);

    flash_attn<<<dim3(T_/64, BH_), 256, FLASH_SMEM>>>(qp, kp, vp, ap);

    splitf32<<<(NE/4 + 255)/256, cblk>>>(ap, ah, al, NE);

    gemm_mma<1><<<dim3(EMB_/128, M_/128, 1), 256, GEMM_SMEM>>>(
        ah, al, woh, wol, bo, bo, bo, out, out, out);
}

// round 4
// speedup vs baseline: 5.0253x; 3.2990x over previous
#include <cuda_runtime.h>
#include <cuda_fp16.h>
#include <stdint.h>

#define T_     2048
#define EMB_   1024
#define HEADS_ 16
#define HD_    64
#define B_     2
#define M_     (B_*T_)      // 4096
#define BH_    (B_*HEADS_)  // 32
#define QSCALE 0.18033688f  // log2(e) / 8

// ---------------- scratch --------------------------------------------------
__device__ __half g_Qh[BH_*T_*HD_];   // [bh][t][d], pre-scaled by QSCALE
__device__ __half g_Kh[BH_*T_*HD_];   // [bh][t][d]
__device__ __half g_Vh[BH_*HD_*T_];   // [bh][d][t]
__device__ __half g_Ah[(size_t)M_*EMB_];   // attention out, fp16 [m][emb]
__device__ __half g_x16[(size_t)M_*EMB_];
__device__ __half g_w16[(size_t)3*EMB_*EMB_];
__device__ __half g_wo16[(size_t)EMB_*EMB_];

// ---------------- helpers ---------------------------------------------------
__device__ __forceinline__ uint32_t smem_u32(const void* p) {
    uint32_t a;
    asm("{ .reg .u64 t; cvta.to.shared.u64 t, %1; cvt.u32.u64 %0, t; }" : "=r"(a) : "l"(p));
    return a;
}
__device__ __forceinline__ void cp16(uint32_t dst, const void* src) {
    asm volatile("cp.async.cg.shared.global [%0], [%1], 16;" :: "r"(dst), "l"(src));
}
__device__ __forceinline__ void cp_commit() { asm volatile("cp.async.commit_group;" ::: "memory"); }
template<int N> __device__ __forceinline__ void cp_wait() {
    asm volatile("cp.async.wait_group %0;" :: "n"(N) : "memory");
}
__device__ __forceinline__ void mma_f16(float* c, const uint32_t* a, const uint32_t* b) {
    asm volatile("mma.sync.aligned.m16n8k16.row.col.f32.f16.f16.f32 "
        "{%0,%1,%2,%3}, {%4,%5,%6,%7}, {%8,%9}, {%0,%1,%2,%3};"
        : "+f"(c[0]), "+f"(c[1]), "+f"(c[2]), "+f"(c[3])
        : "r"(a[0]), "r"(a[1]), "r"(a[2]), "r"(a[3]), "r"(b[0]), "r"(b[1]));
}
__device__ __forceinline__ float ex2f(float x) {
    float y; asm("ex2.approx.ftz.f32 %0, %1;" : "=f"(y) : "f"(x)); return y;
}
__device__ __forceinline__ uint32_t packh2(float a, float b) {
    __half2 h = __floats2half2_rn(a, b);
    return *(uint32_t*)&h;
}

// ---------------- fp32 -> fp16 convert --------------------------------------
__global__ void tohalf(const float* __restrict__ s, __half* __restrict__ d, int n) {
    int i = (blockIdx.x * blockDim.x + threadIdx.x) << 2;
    if (i >= n) return;
    float4 v = *(const float4*)(s + i);
    __half2* D = (__half2*)(d + i);
    D[0] = __floats2half2_rn(v.x, v.y);
    D[1] = __floats2half2_rn(v.z, v.w);
}

// ---------------- fp16 HMMA GEMM: 128x128 tile, K=1024 ----------------------
// out = A @ W^T + bias.
// MODE 0: blockIdx.z=0 -> Qh (scaled, [bh][t][d]); z=1 -> Kh; z=2 -> Vh ([bh][d][t])
// MODE 1: fp32 row-major [m][n] to fout
#define BK      64
#define NCH     (EMB_/BK)       // 16
#define GST     72              // half stride (64 + 8 pad)
#define TILE_E  (128*GST)
#define GBUF_E  (2*TILE_E)
#define GEMM_SMEM (2*GBUF_E*2)  // 73728 bytes

template<int MODE>
__global__ void __launch_bounds__(256) gemm_h(
    const __half* __restrict__ A, const __half* __restrict__ W,
    const float* __restrict__ b0, const float* __restrict__ b1,
    const float* __restrict__ b2,
    __half* __restrict__ qo, __half* __restrict__ ko, __half* __restrict__ vo,
    float* __restrict__ fout)
{
    extern __shared__ __half sh[];
    const int tid  = threadIdx.x;
    const int lane = tid & 31;
    const int wid  = tid >> 5;
    const int wm   = wid >> 2;       // 0..1
    const int wn   = wid & 3;        // 0..3
    const int m0   = blockIdx.y << 7;
    const int n0   = blockIdx.x << 7;
    const int z    = (MODE == 0) ? (int)blockIdx.z : 0;

    const __half* Wp  = W + (size_t)z * EMB_ * EMB_;
    const float* bias = (MODE == 0) ? (z == 0 ? b0 : (z == 1 ? b1 : b2)) : b0;

    const uint32_t sb = smem_u32(sh);
    const int lr = tid & 127;
    const int s0 = (tid >> 7) << 2;
    const __half* gA = A  + (size_t)(m0 + lr) * EMB_;
    const __half* gB = Wp + (size_t)(n0 + lr) * EMB_;

    auto load_chunk = [&](int kc, int buf) {
        const uint32_t base = sb + (uint32_t)buf * (GBUF_E * 2);
        const int ke = kc * BK;
#pragma unroll
        for (int s = s0; s < s0 + 4; s++) {
            cp16(base + (uint32_t)lr*144 + s*16, gA + ke + s*8);
            cp16(base + TILE_E*2 + (uint32_t)lr*144 + s*16, gB + ke + s*8);
        }
        cp_commit();
    };

    float acc[4][4][4] = {};
    load_chunk(0, 0);

    for (int kc = 0; kc < NCH; kc++) {
        const int buf = kc & 1;
        if (kc + 1 < NCH) { load_chunk(kc + 1, buf ^ 1); cp_wait<1>(); }
        else              { cp_wait<0>(); }
        __syncthreads();

        const __half* sA = sh + buf * GBUF_E;
        const __half* sB = sA + TILE_E;

#pragma unroll
        for (int ks = 0; ks < 4; ks++) {
            const int kb = ks * 16 + ((lane & 3) << 1);
            uint32_t bf[4][2];
#pragma unroll
            for (int nf = 0; nf < 4; nf++) {
                const int n = wn * 32 + nf * 8 + (lane >> 2);
                bf[nf][0] = *(const uint32_t*)&sB[n * GST + kb];
                bf[nf][1] = *(const uint32_t*)&sB[n * GST + kb + 8];
            }
#pragma unroll
            for (int mf = 0; mf < 4; mf++) {
                const int r = wm * 64 + mf * 16 + (lane >> 2);
                uint32_t a[4];
                a[0] = *(const uint32_t*)&sA[ r      * GST + kb];
                a[1] = *(const uint32_t*)&sA[(r + 8) * GST + kb];
                a[2] = *(const uint32_t*)&sA[ r      * GST + kb + 8];
                a[3] = *(const uint32_t*)&sA[(r + 8) * GST + kb + 8];
#pragma unroll
                for (int nf = 0; nf < 4; nf++)
                    mma_f16(acc[mf][nf], a, bf[nf]);
            }
        }
        __syncthreads();
    }

    // -------- epilogue --------
#pragma unroll
    for (int mf = 0; mf < 4; mf++) {
#pragma unroll
        for (int nf = 0; nf < 4; nf++) {
#pragma unroll
            for (int h = 0; h < 2; h++) {
                const int m = m0 + wm * 64 + mf * 16 + (lane >> 2) + h * 8;
                const int n = n0 + wn * 32 + nf * 8 + ((lane & 3) << 1);
                const float v0 = acc[mf][nf][h*2 + 0] + bias[n];
                const float v1 = acc[mf][nf][h*2 + 1] + bias[n + 1];
                if (MODE == 0) {
                    const int bb = m >> 11, t = m & (T_ - 1);
                    const int hh = n >> 6,  d = n & 63;
                    const int bh = bb * HEADS_ + hh;
                    if (z == 0) {
                        *(uint32_t*)&qo[((size_t)bh * T_ + t) * HD_ + d] =
                            packh2(v0 * QSCALE, v1 * QSCALE);
                    } else if (z == 1) {
                        *(uint32_t*)&ko[((size_t)bh * T_ + t) * HD_ + d] =
                            packh2(v0, v1);
                    } else {
                        vo[((size_t)bh * HD_ + d    ) * T_ + t] = __float2half(v0);
                        vo[((size_t)bh * HD_ + d + 1) * T_ + t] = __float2half(v1);
                    }
                } else {
                    *(float2*)&fout[(size_t)m * EMB_ + n] = make_float2(v0, v1);
                }
            }
        }
    }
}

// ---------------- HMMA flash attention --------------------------------------
// q-tile 128 rows, k-tiles of 64. 4 warps (warp = 32 q-rows).
// Q pre-scaled by log2e/8 -> softmax via ex2.
#define FST 72
#define FQ_E (128*FST)       // 9216 halves
#define FKV_E (64*FST)       // 4608 halves
#define FLASH_SMEM ((FQ_E + 4*FKV_E)*2)   // 55296 bytes

__global__ void __launch_bounds__(128) flash_h(
    const __half* __restrict__ Q, const __half* __restrict__ K,
    const __half* __restrict__ V, __half* __restrict__ Aout)
{
    extern __shared__ __half fsh[];
    __half* Qs = fsh;                 // [128][72]
    __half* Ks = fsh + FQ_E;          // 2 bufs [64][72]
    __half* Vs = fsh + FQ_E + 2*FKV_E;

    const int qi  = (int)gridDim.x - 1 - (int)blockIdx.x;  // heavy tiles first
    const int bh  = blockIdx.y;
    const int q0  = qi << 7;
    const int tid = threadIdx.x;
    const int lane = tid & 31;
    const int w   = tid >> 5;
    const int njt = 2 * qi + 2;

    const __half* Qg = Q + ((size_t)bh * T_ + q0) * HD_;
    const __half* Kg = K + (size_t)bh * T_ * HD_;
    const __half* Vg = V + (size_t)bh * HD_ * T_;
    const uint32_t sQ = smem_u32(Qs);
    const uint32_t sK = smem_u32(Ks);
    const uint32_t sV = smem_u32(Vs);

    // Q tile: 128 rows x 64d (128B = 8 segs), 1 row/thread
#pragma unroll
    for (int s = 0; s < 8; s++)
        cp16(sQ + (uint32_t)tid*144 + s*16, Qg + (size_t)tid*HD_ + s*8);
    cp_commit();

    auto loadKV = [&](int jt, int buf) {
        const int k0 = jt << 6;
        const int r  = tid >> 1;
        const int sb_ = (tid & 1) << 2;
#pragma unroll
        for (int s = sb_; s < sb_ + 4; s++) {
            cp16(sK + buf*(FKV_E*2) + (uint32_t)r*144 + s*16, Kg + (size_t)(k0 + r)*HD_ + s*8);
            cp16(sV + buf*(FKV_E*2) + (uint32_t)r*144 + s*16, Vg + (size_t)r*T_ + k0 + s*8);
        }
        cp_commit();
    };
    loadKV(0, 0);

    float o[2][8][4] = {};
    float mi[2][2], li[2][2];
#pragma unroll
    for (int a = 0; a < 2; a++)
#pragma unroll
        for (int b = 0; b < 2; b++) { mi[a][b] = -1e30f; li[a][b] = 0.f; }

    for (int jt = 0; jt < njt; jt++) {
        const int buf = jt & 1;
        if (jt + 1 < njt) { loadKV(jt + 1, buf ^ 1); cp_wait<1>(); }
        else              { cp_wait<0>(); }
        __syncthreads();

        const __half* Kb = Ks + buf * FKV_E;
        const __half* Vb = Vs + buf * FKV_E;

        // ---- S = Q @ K^T (log2-scaled) ----
        float s[2][8][4] = {};
#pragma unroll
        for (int ks = 0; ks < 4; ks++) {
            const int kb = ks * 16 + ((lane & 3) << 1);
            uint32_t bf[8][2];
#pragma unroll
            for (int nf = 0; nf < 8; nf++) {
                const int n = nf * 8 + (lane >> 2);
                bf[nf][0] = *(const uint32_t*)&Kb[n * FST + kb];
                bf[nf][1] = *(const uint32_t*)&Kb[n * FST + kb + 8];
            }
#pragma unroll
            for (int mf = 0; mf < 2; mf++) {
                const int r = w * 32 + mf * 16 + (lane >> 2);
                uint32_t a[4];
                a[0] = *(const uint32_t*)&Qs[ r      * FST + kb];
                a[1] = *(const uint32_t*)&Qs[(r + 8) * FST + kb];
                a[2] = *(const uint32_t*)&Qs[ r      * FST + kb + 8];
                a[3] = *(const uint32_t*)&Qs[(r + 8) * FST + kb + 8];
#pragma unroll
                for (int nf = 0; nf < 8; nf++)
                    mma_f16(s[mf][nf], a, bf[nf]);
            }
        }

        // ---- causal mask (only last 2 tiles touch the diagonal) ----
        const int k0 = jt << 6;
        if (jt >= njt - 2) {
#pragma unroll
            for (int mf = 0; mf < 2; mf++)
#pragma unroll
                for (int nf = 0; nf < 8; nf++)
#pragma unroll
                    for (int c = 0; c < 4; c++) {
                        const int qr = q0 + w * 32 + mf * 16 + (lane >> 2) + (c >> 1) * 8;
                        const int kc = k0 + nf * 8 + ((lane & 3) << 1) + (c & 1);
                        if (kc > qr) s[mf][nf][c] = -1e30f;
                    }
        }

        // ---- online softmax ----
        float fac[2][2];
#pragma unroll
        for (int mf = 0; mf < 2; mf++)
#pragma unroll
            for (int h = 0; h < 2; h++) {
                float mx = -1e30f;
#pragma unroll
                for (int nf = 0; nf < 8; nf++)
                    mx = fmaxf(mx, fmaxf(s[mf][nf][2*h], s[mf][nf][2*h + 1]));
                mx = fmaxf(mx, __shfl_xor_sync(0xffffffffu, mx, 1));
                mx = fmaxf(mx, __shfl_xor_sync(0xffffffffu, mx, 2));
                const float mn = fmaxf(mi[mf][h], mx);
                fac[mf][h] = ex2f(mi[mf][h] - mn);
                mi[mf][h] = mn;
            }
#pragma unroll
        for (int mf = 0; mf < 2; mf++)
#pragma unroll
            for (int h = 0; h < 2; h++) {
                float r = 0.f;
#pragma unroll
                for (int nf = 0; nf < 8; nf++) {
                    float p0 = ex2f(s[mf][nf][2*h]     - mi[mf][h]);
                    float p1 = ex2f(s[mf][nf][2*h + 1] - mi[mf][h]);
                    s[mf][nf][2*h]     = p0;
                    s[mf][nf][2*h + 1] = p1;
                    r += p0 + p1;
                }
                r += __shfl_xor_sync(0xffffffffu, r, 1);
                r += __shfl_xor_sync(0xffffffffu, r, 2);
                li[mf][h] = li[mf][h] * fac[mf][h] + r;
            }
#pragma unroll
        for (int mf = 0; mf < 2; mf++)
#pragma unroll
            for (int df = 0; df < 8; df++) {
                o[mf][df][0] *= fac[mf][0]; o[mf][df][1] *= fac[mf][0];
                o[mf][df][2] *= fac[mf][1]; o[mf][df][3] *= fac[mf][1];
            }

        // ---- O += P @ V  (P: in-register C->A fragment conversion) ----
#pragma unroll
        for (int kf = 0; kf < 4; kf++) {
            const int kb = kf * 16 + ((lane & 3) << 1);
            uint32_t vb[8][2];
#pragma unroll
            for (int df = 0; df < 8; df++) {
                const int n = df * 8 + (lane >> 2);
                vb[df][0] = *(const uint32_t*)&Vb[n * FST + kb];
                vb[df][1] = *(const uint32_t*)&Vb[n * FST + kb + 8];
            }
#pragma unroll
            for (int mf = 0; mf < 2; mf++) {
                uint32_t pa[4];
                pa[0] = packh2(s[mf][2*kf][0],     s[mf][2*kf][1]);
                pa[1] = packh2(s[mf][2*kf][2],     s[mf][2*kf][3]);
                pa[2] = packh2(s[mf][2*kf + 1][0], s[mf][2*kf + 1][1]);
                pa[3] = packh2(s[mf][2*kf + 1][2], s[mf][2*kf + 1][3]);
#pragma unroll
                for (int df = 0; df < 8; df++)
                    mma_f16(o[mf][df], pa, vb[df]);
            }
        }
        __syncthreads();
    }

    // ---- write O/li -> fp16 A [m][emb] ----
    const int bidx = bh >> 4;
    const int hh   = bh & 15;
    float inv[2][2];
#pragma unroll
    for (int mf = 0; mf < 2; mf++)
#pragma unroll
        for (int h = 0; h < 2; h++) inv[mf][h] = __frcp_rn(li[mf][h]);

#pragma unroll
    for (int mf = 0; mf < 2; mf++)
#pragma unroll
        for (int h = 0; h < 2; h++) {
            const int t = q0 + w * 32 + mf * 16 + (lane >> 2) + h * 8;
            const size_t m = (size_t)bidx * T_ + t;
#pragma unroll
            for (int df = 0; df < 8; df++) {
                const int col = hh * 64 + df * 8 + ((lane & 3) << 1);
                *(uint32_t*)&Aout[m * EMB_ + col] =
                    packh2(o[mf][df][2*h] * inv[mf][h], o[mf][df][2*h + 1] * inv[mf][h]);
            }
        }
}

// ---------------------------------------------------------------------------
extern "C" void kernel_launch(void* const* d_in, const int* in_sizes, int n_in,
                              void* d_out, int out_size)
{
    const float* x  = (const float*)d_in[0];
    const float* Wq = (const float*)d_in[1];
    const float* bq = (const float*)d_in[2];
    const float* Wk = (const float*)d_in[3];
    const float* bk = (const float*)d_in[4];
    const float* Wv = (const float*)d_in[5];
    const float* bv = (const float*)d_in[6];
    const float* Wo = (const float*)d_in[7];
    const float* bo = (const float*)d_in[8];
    float* out = (float*)d_out;

    __half *qh, *kh, *vh, *ah, *x16, *w16, *wo16;
    cudaGetSymbolAddress((void**)&qh,   g_Qh);
    cudaGetSymbolAddress((void**)&kh,   g_Kh);
    cudaGetSymbolAddress((void**)&vh,   g_Vh);
    cudaGetSymbolAddress((void**)&ah,   g_Ah);
    cudaGetSymbolAddress((void**)&x16,  g_x16);
    cudaGetSymbolAddress((void**)&w16,  g_w16);
    cudaGetSymbolAddress((void**)&wo16, g_wo16);

    cudaFuncSetAttribute(flash_h,   cudaFuncAttributeMaxDynamicSharedMemorySize, FLASH_SMEM);
    cudaFuncSetAttribute(gemm_h<0>, cudaFuncAttributeMaxDynamicSharedMemorySize, GEMM_SMEM);
    cudaFuncSetAttribute(gemm_h<1>, cudaFuncAttributeMaxDynamicSharedMemorySize, GEMM_SMEM);

    const int NE = M_ * EMB_;
    const int NW = EMB_ * EMB_;
    dim3 cblk(256);

    tohalf<<<(NE/4 + 255)/256, cblk>>>(x,  x16, NE);
    tohalf<<<(NW/4 + 255)/256, cblk>>>(Wq, w16 + 0*(size_t)NW, NW);
    tohalf<<<(NW/4 + 255)/256, cblk>>>(Wk, w16 + 1*(size_t)NW, NW);
    tohalf<<<(NW/4 + 255)/256, cblk>>>(Wv, w16 + 2*(size_t)NW, NW);
    tohalf<<<(NW/4 + 255)/256, cblk>>>(Wo, wo16, NW);

    gemm_h<0><<<dim3(EMB_/128, M_/128, 3), 256, GEMM_SMEM>>>(
        x16, w16, bq, bk, bv, qh, kh, vh, nullptr);

    flash_h<<<dim3(T_/128, BH_), 128, FLASH_SMEM>>>(qh, kh, vh, ah);

    gemm_h<1><<<dim3(EMB_/128, M_/128, 1), 256, GEMM_SMEM>>>(
        ah, wo16, bo, bo, bo, nullptr, nullptr, nullptr, out);
}